// round 15
// baseline (speedup 1.0000x reference)
#include <cuda_runtime.h>
#include <cuda_bf16.h>
#include <math.h>
#include <stdint.h>

// Problem constants
#define B_  2
#define S_  2048
#define H_  2048
#define NH_ 16
#define HD_ 128
#define ROWS_ (B_ * S_)        // 4096
#define QKV_N (3 * H_)         // 6144

// ---------------- scratch (static device globals; no allocation) ----------------
__device__ float g_q[(size_t)B_ * NH_ * S_ * HD_];        // [b,h,s,d] tf32-rounded (log2e folded)
__device__ float g_k[(size_t)B_ * NH_ * S_ * HD_];        // [b,h,s,d] tf32-rounded
__device__ float g_v[(size_t)B_ * NH_ * S_ * HD_];        // [b,h,d,s] tf32-rounded
__device__ float g_ctx[(size_t)ROWS_ * H_];               // [b*s, h*d] tf32-rounded
__device__ float g_hid_tf[(size_t)ROWS_ * H_];            // tf32-rounded A
__device__ float g_wct[(size_t)QKV_N * H_];               // Wc^T [6144][2048] tf32
__device__ float g_wpt[(size_t)H_ * H_];                  // Wp^T [2048][2048] tf32

// ---------------- helpers ----------------
__device__ __forceinline__ uint32_t f2tf(float x) {
    uint32_t r;
    asm("cvt.rna.tf32.f32 %0, %1;" : "=r"(r) : "f"(x));
    return r;
}
__device__ __forceinline__ float f2tff(float x) { return __uint_as_float(f2tf(x)); }

__device__ __forceinline__ void mma_tf32(float* c, const uint32_t* a, const uint32_t* b) {
    asm volatile(
        "mma.sync.aligned.m16n8k8.row.col.f32.tf32.tf32.f32 "
        "{%0,%1,%2,%3}, {%4,%5,%6,%7}, {%8,%9}, {%0,%1,%2,%3};\n"
        : "+f"(c[0]), "+f"(c[1]), "+f"(c[2]), "+f"(c[3])
        : "r"(a[0]), "r"(a[1]), "r"(a[2]), "r"(a[3]),
          "r"(b[0]), "r"(b[1]));
}
__device__ __forceinline__ void ldsm4(uint32_t* r, uint32_t addr) {
    asm volatile("ldmatrix.sync.aligned.m8n8.x4.shared.b16 {%0,%1,%2,%3}, [%4];"
        : "=r"(r[0]), "=r"(r[1]), "=r"(r[2]), "=r"(r[3]) : "r"(addr));
}
__device__ __forceinline__ uint32_t smem_u32(const void* p) {
    return (uint32_t)__cvta_generic_to_shared(p);
}
__device__ __forceinline__ void cp16(uint32_t dst, const void* src) {
    asm volatile("cp.async.cg.shared.global [%0], [%1], 16;" :: "r"(dst), "l"(src));
}
__device__ __forceinline__ void cp_commit() {
    asm volatile("cp.async.commit_group;");
}
template<int N> __device__ __forceinline__ void cp_wait() {
    asm volatile("cp.async.wait_group %0;" :: "n"(N));
}

// ---------------- merged preprocessing (float4 transposes) ----------------
__device__ __forceinline__ void wtrans_body4(
    const float* __restrict__ in, float* __restrict__ out,
    int K, int N, int k0, int n0, int tid, float (*t)[33])
{
    const int x4 = tid & 7, y = tid >> 3;
    {
        float4 v = *(const float4*)(in + (size_t)(k0 + y) * N + n0 + x4 * 4);
        t[y][x4 * 4 + 0] = v.x;
        t[y][x4 * 4 + 1] = v.y;
        t[y][x4 * 4 + 2] = v.z;
        t[y][x4 * 4 + 3] = v.w;
    }
    __syncthreads();
    {
        float4 v;
        v.x = f2tff(t[x4 * 4 + 0][y]);
        v.y = f2tff(t[x4 * 4 + 1][y]);
        v.z = f2tff(t[x4 * 4 + 2][y]);
        v.w = f2tff(t[x4 * 4 + 3][y]);
        *(float4*)(out + (size_t)(n0 + y) * K + k0 + x4 * 4) = v;
    }
}

#define PREP_H 8192
#define PREP_WC 12288
#define PREP_WP 4096

__global__ __launch_bounds__(256) void prep_all(
    const float* __restrict__ hidden, const float* __restrict__ Wc,
    const float* __restrict__ Wp,
    float* __restrict__ hid_tf, float* __restrict__ wct, float* __restrict__ wpt)
{
    __shared__ float t[32][33];
    const int bid = blockIdx.x;
    if (bid < PREP_H) {
        int i = bid * 256 + threadIdx.x;
        float4 v = ((const float4*)hidden)[i];
        v.x = f2tff(v.x); v.y = f2tff(v.y); v.z = f2tff(v.z); v.w = f2tff(v.w);
        ((float4*)hid_tf)[i] = v;
    } else if (bid < PREP_H + PREP_WC) {
        int id = bid - PREP_H;
        wtrans_body4(Wc, wct, H_, QKV_N, (id & 63) * 32, (id >> 6) * 32, threadIdx.x, t);
    } else {
        int id = bid - PREP_H - PREP_WC;
        wtrans_body4(Wp, wpt, H_, H_, (id & 63) * 32, (id >> 6) * 32, threadIdx.x, t);
    }
}

// ---------------- TF32 GEMM mainloop: 128x128, BK=32, 3 stages ----------------
#define GSTR 36
#define GT_ST (128 * GSTR)
#define G_ST  (2 * GT_ST)
#define GEMM_SMEM (3 * G_ST * 4)    // 110592 B
#define TSSTR 132

// quarter-split prefetch: 2 cp16 per window (A0,A1,B0,B1 at ks 0..3)
#define ISSUE_A_HALF(kt, st, hh)                                                  \
    do {                                                                          \
        const float* Asrc = Ab + (kt) * 32;                                       \
        uint32_t au = as_u + (uint32_t)((st) * G_ST * 4);                         \
        _Pragma("unroll")                                                         \
        for (int i = 0; i < 2; i++) {                                             \
            int ch = tid + 256 * (i + 2 * (hh));                                  \
            int r = ch >> 3, c2 = (ch & 7) << 2;                                  \
            cp16(au + (uint32_t)((r * GSTR + c2) * 4), Asrc + (size_t)r * K + c2);\
        }                                                                         \
    } while (0)
#define ISSUE_B_HALF(kt, st, hh)                                                  \
    do {                                                                          \
        const float* Bsrc = Bb + (kt) * 32;                                       \
        uint32_t bu = as_u + (uint32_t)((st) * G_ST * 4) + (uint32_t)(GT_ST * 4); \
        _Pragma("unroll")                                                         \
        for (int i = 0; i < 2; i++) {                                             \
            int ch = tid + 256 * (i + 2 * (hh));                                  \
            int r = ch >> 3, c2 = (ch & 7) << 2;                                  \
            cp16(bu + (uint32_t)((r * GSTR + c2) * 4), Bsrc + (size_t)r * K + c2);\
        }                                                                         \
    } while (0)

#define GEMM_MAINLOOP(Aptr, Bptr)                                                 \
    const uint32_t as_u = smem_u32(gsm);                                          \
    const int tid = threadIdx.x;                                                  \
    const int bx = blockIdx.x, by = blockIdx.y;                                   \
    const int warp = tid >> 5, lane = tid & 31;                                   \
    const int wm = (warp & 1) * 64;                                               \
    const int wn = (warp >> 1) * 32;                                              \
    const int lr = lane >> 2;                                                     \
    const int lc = lane & 3;                                                      \
    const int la_m = lane & 15;                                                   \
    const int la_k = (lane >> 4) << 2;                                            \
    const int lb_r = (lane & 7) + ((lane >> 4) << 3);                             \
    const int lb_c = ((lane >> 3) & 1) << 2;                                      \
    const uint32_t a_lane = as_u + (uint32_t)(((wm + la_m) * GSTR + la_k) * 4);   \
    const uint32_t b_lane = as_u + (uint32_t)(GT_ST * 4)                          \
                          + (uint32_t)(((wn + lb_r) * GSTR + lb_c) * 4);          \
    const float* Ab = (Aptr) + (size_t)(by * 128) * K;                            \
    const float* Bb = (Bptr) + (size_t)(bx * 128) * K;                            \
    const int KT = K >> 5;                                                        \
    ISSUE_A_HALF(0, 0, 0); ISSUE_A_HALF(0, 0, 1);                                 \
    ISSUE_B_HALF(0, 0, 0); ISSUE_B_HALF(0, 0, 1); cp_commit();                    \
    ISSUE_A_HALF(1, 1, 0); ISSUE_A_HALF(1, 1, 1);                                 \
    ISSUE_B_HALF(1, 1, 0); ISSUE_B_HALF(1, 1, 1); cp_commit();                    \
    float c[4][4][4];                                                             \
    _Pragma("unroll")                                                             \
    for (int mt = 0; mt < 4; mt++)                                                \
        _Pragma("unroll")                                                         \
        for (int nt = 0; nt < 4; nt++)                                            \
            _Pragma("unroll")                                                     \
            for (int j = 0; j < 4; j++) c[mt][nt][j] = 0.f;                       \
    for (int kt = 0; kt < KT; kt++) {                                             \
        cp_wait<1>();                                                             \
        __syncthreads();                                                          \
        const uint32_t stoff = (uint32_t)((kt % 3) * G_ST * 4);                   \
        const uint32_t a_st = a_lane + stoff;                                     \
        const uint32_t b_st = b_lane + stoff;                                     \
        const bool pre = (kt + 2 < KT);                                           \
        const int pst = (kt + 2) % 3;                                             \
        _Pragma("unroll")                                                         \
        for (int ks = 0; ks < 4; ks++) {                                          \
            const int kb = ks * 8;                                                \
            uint32_t af[4][4], bf[4][2];                                          \
            _Pragma("unroll")                                                     \
            for (int mt = 0; mt < 4; mt++)                                        \
                ldsm4(af[mt], a_st + (uint32_t)((mt * 16 * GSTR + kb) * 4));      \
            _Pragma("unroll")                                                     \
            for (int p = 0; p < 2; p++) {                                         \
                uint32_t r[4];                                                    \
                ldsm4(r, b_st + (uint32_t)((p * 16 * GSTR + kb) * 4));            \
                bf[2 * p][0] = r[0]; bf[2 * p][1] = r[1];                         \
                bf[2 * p + 1][0] = r[2]; bf[2 * p + 1][1] = r[3];                 \
            }                                                                     \
            _Pragma("unroll")                                                     \
            for (int mt = 0; mt < 4; mt++)                                        \
                _Pragma("unroll")                                                 \
                for (int nt = 0; nt < 4; nt++)                                    \
                    mma_tf32(c[mt][nt], af[mt], bf[nt]);                          \
            if (ks == 0 && pre) { ISSUE_A_HALF(kt + 2, pst, 0); }                 \
            if (ks == 1 && pre) { ISSUE_A_HALF(kt + 2, pst, 1); }                 \
            if (ks == 2 && pre) { ISSUE_B_HALF(kt + 2, pst, 0); }                 \
            if (ks == 3) {                                                        \
                if (pre) { ISSUE_B_HALF(kt + 2, pst, 1); }                        \
                cp_commit();                                                      \
            }                                                                     \
        }                                                                         \
    }

// ---------------- plain GEMM (proj): C = A @ Bt^T + bias ----------------
__global__ __launch_bounds__(256, 2) void gemm_tf32(
    const float* __restrict__ A, const float* __restrict__ Bt,
    const float* __restrict__ bias, float* __restrict__ C,
    int M, int N, int K)
{
    extern __shared__ float gsm[];
    GEMM_MAINLOOP(A, Bt)

#pragma unroll
    for (int mt = 0; mt < 4; mt++) {
        int row = by * 128 + wm + mt * 16 + lr;
#pragma unroll
        for (int nt = 0; nt < 4; nt++) {
            int col = bx * 128 + wn + nt * 8 + 2 * lc;
            float b0 = bias[col], b1 = bias[col + 1];
            float2 v0 = { c[mt][nt][0] + b0, c[mt][nt][1] + b1 };
            float2 v1 = { c[mt][nt][2] + b0, c[mt][nt][3] + b1 };
            *(float2*)(C + (size_t)row * N + col) = v0;
            *(float2*)(C + (size_t)(row + 8) * N + col) = v1;
        }
    }
}

// ---------------- fused QKV GEMM: rope+logn for Q/K, transpose for V ----------------
__global__ __launch_bounds__(256, 2) void gemm_qkv(
    const float* __restrict__ A, const float* __restrict__ Bt,
    const float* __restrict__ bias,
    const float* __restrict__ cosb, const float* __restrict__ sinb,
    const float* __restrict__ logn,
    float* __restrict__ Qo, float* __restrict__ Ko, float* __restrict__ Vo,
    int M, int N, int K)
{
    extern __shared__ float gsm[];
    GEMM_MAINLOOP(A, Bt)

    __syncthreads();
    float* ts = gsm;                 // [128][TSSTR]
    const bool isV = (bx >= 32);

#pragma unroll
    for (int mt = 0; mt < 4; mt++) {
        int row = wm + mt * 16 + lr;
#pragma unroll
        for (int nt = 0; nt < 4; nt++) {
            int col = wn + nt * 8 + 2 * lc;
            float b0 = bias[bx * 128 + col], b1 = bias[bx * 128 + col + 1];
            float v00 = c[mt][nt][0] + b0, v01 = c[mt][nt][1] + b1;
            float v10 = c[mt][nt][2] + b0, v11 = c[mt][nt][3] + b1;
            if (!isV) {
                ts[row * TSSTR + col] = v00;
                ts[row * TSSTR + col + 1] = v01;
                ts[(row + 8) * TSSTR + col] = v10;
                ts[(row + 8) * TSSTR + col + 1] = v11;
            } else {
                ts[col * TSSTR + row] = v00;
                ts[(col + 1) * TSSTR + row] = v01;
                ts[col * TSSTR + row + 8] = v10;
                ts[(col + 1) * TSSTR + row + 8] = v11;
            }
        }
    }
    __syncthreads();

    if (!isV) {
        const bool isQ = (bx < 16);
        const int h = bx & 15;
        float* dst = isQ ? Qo : Ko;
        for (int t = tid; t < 128 * 32; t += 256) {
            int r = t >> 5, c4 = (t & 31) << 2;
            int sg = by * 128 + r;
            int b = sg >> 11;
            int s = sg & (S_ - 1);
            const float* rowp = ts + r * TSSTR;
            float4 v  = *(const float4*)(rowp + c4);
            int dro = (c4 < 64) ? (c4 + 64) : (c4 - 64);
            float4 vo = *(const float4*)(rowp + dro);
            float4 cv = *(const float4*)(cosb + (size_t)s * HD_ + c4);
            float4 sv = *(const float4*)(sinb + (size_t)s * HD_ + c4);
            float sgn = (c4 < 64) ? -1.f : 1.f;
            float4 res;
            res.x = v.x * cv.x + sgn * vo.x * sv.x;
            res.y = v.y * cv.y + sgn * vo.y * sv.y;
            res.z = v.z * cv.z + sgn * vo.z * sv.z;
            res.w = v.w * cv.w + sgn * vo.w * sv.w;
            if (isQ) {
                float ln = logn[s] * 0.08838834764831845f * 1.4426950408889634f;
                res.x *= ln; res.y *= ln; res.z *= ln; res.w *= ln;
            }
            size_t oidx = (((size_t)(b * NH_ + h) * S_ + s) << 7) + c4;
            uint4 u = { f2tf(res.x), f2tf(res.y), f2tf(res.z), f2tf(res.w) };
            *(uint4*)(dst + oidx) = u;
        }
    } else {
        const int h = bx - 32;
        const int b = by >> 4;
        const int sl0 = (by & 15) * 128;
        for (int t = tid; t < 128 * 32; t += 256) {
            int d = t >> 5, s4 = (t & 31) << 2;
            float4 v = *(const float4*)(ts + d * TSSTR + s4);
            uint4 u = { f2tf(v.x), f2tf(v.y), f2tf(v.z), f2tf(v.w) };
            size_t oidx = ((size_t)((b * NH_ + h) * HD_ + d) * S_) + sl0 + s4;
            *(uint4*)(Vo + oidx) = u;
        }
    }
}

// ---------------- Flash attention v6: 2 barriers/tile, finer KV issue split ----------------
#define FBQ 128
#define FBKT 64
#define KSTR 132
#define VSTR 68
#define PSTR 68
#define FK_ST (FBKT * KSTR)
#define FV_ST (HD_ * VSTR)
#define OFF_V (2 * FK_ST)
#define OFF_P (OFF_V + 2 * FV_ST)
#define OFF_AL (OFF_P + FBQ * PSTR)
#define FLASH_SMEM ((OFF_AL + 2 * FBQ) * 4)   // 173056 B

__global__ __launch_bounds__(256) void flash_tc(
    const float* __restrict__ Q, const float* __restrict__ K,
    const float* __restrict__ V, float* __restrict__ ctx)
{
    extern __shared__ float fsm[];
    uint32_t* Ps = (uint32_t*)(fsm + OFF_P);
    float* al_s = fsm + OFF_AL;
    float* l_s  = al_s + FBQ;
    const uint32_t ks_u = smem_u32(fsm);
    const uint32_t vs_u = ks_u + (uint32_t)(OFF_V * 4);
    const uint32_t ps_u = smem_u32(Ps);

    const int qt = (S_ / FBQ - 1) - blockIdx.x;
    const int bh = blockIdx.y;
    const int tid = threadIdx.x;
    const int warp = tid >> 5, lane = tid & 31;
    const int lr = lane >> 2;
    const int lc = lane & 3;

    const int la_m = lane & 15;
    const int la_k = (lane >> 4) << 2;
    const int lb_r = (lane & 7) + ((lane >> 4) << 3);
    const int lb_c = ((lane >> 3) & 1) << 2;

    const int wm2 = (warp & 1) * 64;
    const int wn2 = (warp >> 1) * 32;
    const uint32_t p_lane = ps_u + (uint32_t)(((wm2 + la_m) * PSTR + la_k) * 4);

    const float* Qb = Q + ((size_t)bh * S_ + qt * FBQ) * HD_;
    const float* Kb = K + (size_t)bh * S_ * HD_;
    const float* Vb = V + (size_t)bh * HD_ * S_;

    for (int t = tid; t < FBQ * (HD_ / 4); t += 256) {
        int r = t >> 5, c4 = (t & 31) << 2;
        *(uint4*)(fsm + r * KSTR + c4) = *(const uint4*)(Qb + (size_t)r * HD_ + c4);
    }
    __syncthreads();
    uint32_t qf[16][4];
    {
        const uint32_t q_lane = ks_u + (uint32_t)(((warp * 16 + la_m) * KSTR + la_k) * 4);
#pragma unroll
        for (int ks = 0; ks < 16; ks++)
            ldsm4(qf[ks], q_lane + (uint32_t)(ks * 8 * 4));
    }
    __syncthreads();

    const int nkt = 2 * qt + 2;

#define ISSUE_K_H(kt, hh)                                                         \
    do {                                                                          \
        const float* ksrc = Kb + (size_t)(kt) * FBKT * HD_;                       \
        uint32_t kdst = ks_u + (uint32_t)(((kt) & 1) * FK_ST * 4);                \
        _Pragma("unroll")                                                         \
        for (int i = 0; i < 4; i++) {                                             \
            int ch = tid + 256 * (i + 4 * (hh));                                  \
            int kr = ch >> 5, kc = (ch & 31) << 2;                                \
            cp16(kdst + (uint32_t)((kr * KSTR + kc) * 4),                         \
                 ksrc + (size_t)kr * HD_ + kc);                                   \
        }                                                                         \
    } while (0)
#define ISSUE_V_F(kt)                                                             \
    do {                                                                          \
        const float* vsrc = Vb + (size_t)(kt) * FBKT;                             \
        uint32_t vdst = vs_u + (uint32_t)(((kt) & 1) * FV_ST * 4);                \
        _Pragma("unroll")                                                         \
        for (int i = 0; i < 8; i++) {                                             \
            int ch = tid + 256 * i;                                               \
            int vr = ch >> 4, vc = (ch & 15) << 2;                                \
            cp16(vdst + (uint32_t)((vr * VSTR + vc) * 4),                         \
                 vsrc + (size_t)vr * S_ + vc);                                    \
        }                                                                         \
    } while (0)

    ISSUE_K_H(0, 0); ISSUE_K_H(0, 1);
    ISSUE_V_F(0);
    cp_commit();

    float m0 = -1e30f, m1 = -1e30f;
    float l0 = 0.f, l1 = 0.f;
    float o[4][4][4];
#pragma unroll
    for (int mt = 0; mt < 4; mt++)
#pragma unroll
        for (int nt = 0; nt < 4; nt++)
#pragma unroll
            for (int j = 0; j < 4; j++) o[mt][nt][j] = 0.f;

    const int r0 = warp * 16 + lr;
    const int g0 = qt * FBQ + r0;
    const int g1 = g0 + 8;

    for (int kt = 0; kt < nkt; kt++) {
        cp_wait<0>();                      // KV(kt) resident
        __syncthreads();                   // + all PV(kt-1) reads finished

        const bool pre = (kt + 1 < nkt);
        if (pre) { ISSUE_K_H(kt + 1, 0); } // first half of K prefetch

        const uint32_t kst_u = ks_u + (uint32_t)((kt & 1) * FK_ST * 4);
        const uint32_t vst_u = vs_u + (uint32_t)((kt & 1) * FV_ST * 4);
        const uint32_t k_lane = kst_u + (uint32_t)((lb_r * KSTR + lb_c) * 4);

        float s[8][4];
#pragma unroll
        for (int nt = 0; nt < 8; nt++)
#pragma unroll
            for (int j = 0; j < 4; j++) s[nt][j] = 0.f;

        uint32_t kf[2][4][4];
#pragma unroll
        for (int p = 0; p < 4; p++)
            ldsm4(kf[0][p], k_lane + (uint32_t)((p * 16 * KSTR) * 4));
#pragma unroll
        for (int ksx = 0; ksx < 16; ksx++) {
            const int cur = ksx & 1;
            if (ksx < 15) {
                const int kbn = (ksx + 1) * 8;
#pragma unroll
                for (int p = 0; p < 4; p++)
                    ldsm4(kf[cur ^ 1][p], k_lane + (uint32_t)((p * 16 * KSTR + kbn) * 4));
            }
#pragma unroll
            for (int p = 0; p < 4; p++) {
                mma_tf32(s[2 * p], qf[ksx], kf[cur][p]);
                mma_tf32(s[2 * p + 1], qf[ksx], kf[cur][p] + 2);
            }
            if (ksx == 0 && pre) { ISSUE_K_H(kt + 1, 1); }   // second K half
            if (ksx == 1) {                                   // V deferred further
                if (pre) { ISSUE_V_F(kt + 1); }
                cp_commit();
            }
        }

        if (kt * FBKT + FBKT - 1 > qt * FBQ + warp * 16) {
#pragma unroll
            for (int nt = 0; nt < 8; nt++) {
                int colb = kt * FBKT + nt * 8 + 2 * lc;
                if (colb > g0)     s[nt][0] = -1e30f;
                if (colb + 1 > g0) s[nt][1] = -1e30f;
                if (colb > g1)     s[nt][2] = -1e30f;
                if (colb + 1 > g1) s[nt][3] = -1e30f;
            }
        }

        float mx0 = -1e30f, mx1 = -1e30f;
#pragma unroll
        for (int nt = 0; nt < 8; nt++) {
            mx0 = fmaxf(mx0, fmaxf(s[nt][0], s[nt][1]));
            mx1 = fmaxf(mx1, fmaxf(s[nt][2], s[nt][3]));
        }
        mx0 = fmaxf(mx0, __shfl_xor_sync(0xffffffffu, mx0, 1));
        mx0 = fmaxf(mx0, __shfl_xor_sync(0xffffffffu, mx0, 2));
        mx1 = fmaxf(mx1, __shfl_xor_sync(0xffffffffu, mx1, 1));
        mx1 = fmaxf(mx1, __shfl_xor_sync(0xffffffffu, mx1, 2));

        float nm0 = fmaxf(m0, mx0), nm1 = fmaxf(m1, mx1);
        float al0 = exp2f(m0 - nm0), al1 = exp2f(m1 - nm1);
        m0 = nm0; m1 = nm1;

        float sum0 = 0.f, sum1 = 0.f;
#pragma unroll
        for (int nt = 0; nt < 8; nt++) {
            s[nt][0] = exp2f(s[nt][0] - nm0);
            s[nt][1] = exp2f(s[nt][1] - nm0);
            s[nt][2] = exp2f(s[nt][2] - nm1);
            s[nt][3] = exp2f(s[nt][3] - nm1);
            sum0 += s[nt][0] + s[nt][1];
            sum1 += s[nt][2] + s[nt][3];
        }
        sum0 += __shfl_xor_sync(0xffffffffu, sum0, 1);
        sum0 += __shfl_xor_sync(0xffffffffu, sum0, 2);
        sum1 += __shfl_xor_sync(0xffffffffu, sum1, 1);
        sum1 += __shfl_xor_sync(0xffffffffu, sum1, 2);
        l0 = l0 * al0 + sum0;
        l1 = l1 * al1 + sum1;

        if (lc == 0) {
            al_s[r0] = al0;
            al_s[r0 + 8] = al1;
        }

#pragma unroll
        for (int nt = 0; nt < 8; nt++) {
            int colp = nt * 8 + 2 * lc;
            Ps[r0 * PSTR + colp]           = f2tf(s[nt][0]);
            Ps[r0 * PSTR + colp + 1]       = f2tf(s[nt][1]);
            Ps[(r0 + 8) * PSTR + colp]     = f2tf(s[nt][2]);
            Ps[(r0 + 8) * PSTR + colp + 1] = f2tf(s[nt][3]);
        }
        __syncthreads();                   // publish P + al

#pragma unroll
        for (int mt = 0; mt < 4; mt++) {
            float a0 = al_s[wm2 + mt * 16 + lr];
            float a1 = al_s[wm2 + mt * 16 + lr + 8];
#pragma unroll
            for (int nt = 0; nt < 4; nt++) {
                o[mt][nt][0] *= a0; o[mt][nt][1] *= a0;
                o[mt][nt][2] *= a1; o[mt][nt][3] *= a1;
            }
        }

        const uint32_t v_lane = vst_u + (uint32_t)(((wn2 + lb_r) * VSTR + lb_c) * 4);
        uint32_t pa[2][4][4], pb[2][2][4];
#pragma unroll
        for (int mt = 0; mt < 4; mt++)
            ldsm4(pa[0][mt], p_lane + (uint32_t)((mt * 16 * PSTR) * 4));
#pragma unroll
        for (int p = 0; p < 2; p++)
            ldsm4(pb[0][p], v_lane + (uint32_t)((p * 16 * VSTR) * 4));

#pragma unroll
        for (int ksx = 0; ksx < 8; ksx++) {
            const int cur = ksx & 1;
            if (ksx < 7) {
                const int kbn = (ksx + 1) * 8;
#pragma unroll
                for (int mt = 0; mt < 4; mt++)
                    ldsm4(pa[cur ^ 1][mt], p_lane + (uint32_t)((mt * 16 * PSTR + kbn) * 4));
#pragma unroll
                for (int p = 0; p < 2; p++)
                    ldsm4(pb[cur ^ 1][p], v_lane + (uint32_t)((p * 16 * VSTR + kbn) * 4));
            }
#pragma unroll
            for (int mt = 0; mt < 4; mt++) {
                mma_tf32(o[mt][0], pa[cur][mt], pb[cur][0]);
                mma_tf32(o[mt][1], pa[cur][mt], pb[cur][0] + 2);
                mma_tf32(o[mt][2], pa[cur][mt], pb[cur][1]);
                mma_tf32(o[mt][3], pa[cur][mt], pb[cur][1] + 2);
            }
        }
        // no end barrier: next iteration's top barrier protects stage reuse
    }
#undef ISSUE_K_H
#undef ISSUE_V_F

    if (lc == 0) {
        l_s[r0] = l0;
        l_s[r0 + 8] = l1;
    }
    __syncthreads();

    const int b = bh >> 4, h = bh & 15;
#pragma unroll
    for (int mt = 0; mt < 4; mt++) {
        int rloc = wm2 + mt * 16 + lr;
        int row0 = qt * FBQ + rloc;
        float il0 = 1.f / l_s[rloc];
        float il1 = 1.f / l_s[rloc + 8];
        float* out0 = ctx + (size_t)(b * S_ + row0) * H_ + h * HD_ + wn2;
        float* out1 = out0 + (size_t)8 * H_;
#pragma unroll
        for (int nt = 0; nt < 4; nt++) {
            int col = nt * 8 + 2 * lc;
            float2 v0 = { f2tff(o[mt][nt][0] * il0), f2tff(o[mt][nt][1] * il0) };
            float2 v1 = { f2tff(o[mt][nt][2] * il1), f2tff(o[mt][nt][3] * il1) };
            *(float2*)(out0 + col) = v0;
            *(float2*)(out1 + col) = v1;
        }
    }
}

// ---------------- launch ----------------
extern "C" void kernel_launch(void* const* d_in, const int* in_sizes, int n_in,
                              void* d_out, int out_size)
{
    const float* hidden = (const float*)d_in[0];
    const float* cosb   = (const float*)d_in[1];
    const float* sinb   = (const float*)d_in[2];
    // d_in[3]: attention_mask (pure causal -> implemented directly)
    const float* logn   = (const float*)d_in[4];
    const float* Wc     = (const float*)d_in[5];
    const float* bc     = (const float*)d_in[6];
    const float* Wp     = (const float*)d_in[7];
    const float* bp     = (const float*)d_in[8];
    float* out = (float*)d_out;

    float *Q, *Kt, *Vt, *ctx, *hid_tf, *wct, *wpt;
    cudaGetSymbolAddress((void**)&Q,      g_q);
    cudaGetSymbolAddress((void**)&Kt,     g_k);
    cudaGetSymbolAddress((void**)&Vt,     g_v);
    cudaGetSymbolAddress((void**)&ctx,    g_ctx);
    cudaGetSymbolAddress((void**)&hid_tf, g_hid_tf);
    cudaGetSymbolAddress((void**)&wct,    g_wct);
    cudaGetSymbolAddress((void**)&wpt,    g_wpt);

    cudaFuncSetAttribute(gemm_tf32,
                         cudaFuncAttributeMaxDynamicSharedMemorySize, GEMM_SMEM);
    cudaFuncSetAttribute(gemm_qkv,
                         cudaFuncAttributeMaxDynamicSharedMemorySize, GEMM_SMEM);
    cudaFuncSetAttribute(flash_tc,
                         cudaFuncAttributeMaxDynamicSharedMemorySize, FLASH_SMEM);

    // 0) pre-round A + transpose/round weights (one launch)
    prep_all<<<PREP_H + PREP_WC + PREP_WP, 256>>>(hidden, Wc, Wp, hid_tf, wct, wpt);

    // 1) fused QKV GEMM + rope/logn/V-transpose -> g_q, g_k, g_v
    gemm_qkv<<<dim3(QKV_N / 128, ROWS_ / 128), 256, GEMM_SMEM>>>(
        hid_tf, wct, bc, cosb, sinb, logn, Q, Kt, Vt, ROWS_, QKV_N, H_);

    // 2) flash attention -> ctx [4096, 2048]
    flash_tc<<<dim3(S_ / FBQ, B_ * NH_), 256, FLASH_SMEM>>>(Q, Kt, Vt, ctx);

    // 3) out = ctx @ Wp + bp      [4096,2048]
    gemm_tf32<<<dim3(H_ / 128, ROWS_ / 128), 256, GEMM_SMEM>>>(
        ctx, wpt, bp, out, ROWS_, H_, H_);
}

// round 16
// speedup vs baseline: 1.0071x; 1.0071x over previous
#include <cuda_runtime.h>
#include <cuda_bf16.h>
#include <math.h>
#include <stdint.h>

// Problem constants
#define B_  2
#define S_  2048
#define H_  2048
#define NH_ 16
#define HD_ 128
#define ROWS_ (B_ * S_)        // 4096
#define QKV_N (3 * H_)         // 6144

// ---------------- scratch (static device globals; no allocation) ----------------
__device__ float g_q[(size_t)B_ * NH_ * S_ * HD_];        // [b,h,s,d] tf32-rounded (log2e folded)
__device__ float g_k[(size_t)B_ * NH_ * S_ * HD_];        // [b,h,s,d] tf32-rounded
__device__ float g_v[(size_t)B_ * NH_ * S_ * HD_];        // [b,h,d,s] tf32-rounded
__device__ float g_ctx[(size_t)ROWS_ * H_];               // [b*s, h*d] tf32-rounded
__device__ float g_hid_tf[(size_t)ROWS_ * H_];            // tf32-rounded A
__device__ float g_wct[(size_t)QKV_N * H_];               // Wc^T [6144][2048] tf32
__device__ float g_wpt[(size_t)H_ * H_];                  // Wp^T [2048][2048] tf32

// ---------------- helpers ----------------
__device__ __forceinline__ uint32_t f2tf(float x) {
    uint32_t r;
    asm("cvt.rna.tf32.f32 %0, %1;" : "=r"(r) : "f"(x));
    return r;
}
__device__ __forceinline__ float f2tff(float x) { return __uint_as_float(f2tf(x)); }

__device__ __forceinline__ void mma_tf32(float* c, const uint32_t* a, const uint32_t* b) {
    asm volatile(
        "mma.sync.aligned.m16n8k8.row.col.f32.tf32.tf32.f32 "
        "{%0,%1,%2,%3}, {%4,%5,%6,%7}, {%8,%9}, {%0,%1,%2,%3};\n"
        : "+f"(c[0]), "+f"(c[1]), "+f"(c[2]), "+f"(c[3])
        : "r"(a[0]), "r"(a[1]), "r"(a[2]), "r"(a[3]),
          "r"(b[0]), "r"(b[1]));
}
__device__ __forceinline__ void ldsm4(uint32_t* r, uint32_t addr) {
    asm volatile("ldmatrix.sync.aligned.m8n8.x4.shared.b16 {%0,%1,%2,%3}, [%4];"
        : "=r"(r[0]), "=r"(r[1]), "=r"(r[2]), "=r"(r[3]) : "r"(addr));
}
__device__ __forceinline__ uint32_t smem_u32(const void* p) {
    return (uint32_t)__cvta_generic_to_shared(p);
}
__device__ __forceinline__ void cp16(uint32_t dst, const void* src) {
    asm volatile("cp.async.cg.shared.global [%0], [%1], 16;" :: "r"(dst), "l"(src));
}
__device__ __forceinline__ void cp_commit() {
    asm volatile("cp.async.commit_group;");
}
template<int N> __device__ __forceinline__ void cp_wait() {
    asm volatile("cp.async.wait_group %0;" :: "n"(N));
}

// ---------------- merged preprocessing (float4 transposes) ----------------
__device__ __forceinline__ void wtrans_body4(
    const float* __restrict__ in, float* __restrict__ out,
    int K, int N, int k0, int n0, int tid, float (*t)[33])
{
    const int x4 = tid & 7, y = tid >> 3;
    {
        float4 v = *(const float4*)(in + (size_t)(k0 + y) * N + n0 + x4 * 4);
        t[y][x4 * 4 + 0] = v.x;
        t[y][x4 * 4 + 1] = v.y;
        t[y][x4 * 4 + 2] = v.z;
        t[y][x4 * 4 + 3] = v.w;
    }
    __syncthreads();
    {
        float4 v;
        v.x = f2tff(t[x4 * 4 + 0][y]);
        v.y = f2tff(t[x4 * 4 + 1][y]);
        v.z = f2tff(t[x4 * 4 + 2][y]);
        v.w = f2tff(t[x4 * 4 + 3][y]);
        *(float4*)(out + (size_t)(n0 + y) * K + k0 + x4 * 4) = v;
    }
}

#define PREP_H 8192
#define PREP_WC 12288
#define PREP_WP 4096

__global__ __launch_bounds__(256) void prep_all(
    const float* __restrict__ hidden, const float* __restrict__ Wc,
    const float* __restrict__ Wp,
    float* __restrict__ hid_tf, float* __restrict__ wct, float* __restrict__ wpt)
{
    __shared__ float t[32][33];
    const int bid = blockIdx.x;
    if (bid < PREP_H) {
        int i = bid * 256 + threadIdx.x;
        float4 v = ((const float4*)hidden)[i];
        v.x = f2tff(v.x); v.y = f2tff(v.y); v.z = f2tff(v.z); v.w = f2tff(v.w);
        ((float4*)hid_tf)[i] = v;
    } else if (bid < PREP_H + PREP_WC) {
        int id = bid - PREP_H;
        wtrans_body4(Wc, wct, H_, QKV_N, (id & 63) * 32, (id >> 6) * 32, threadIdx.x, t);
    } else {
        int id = bid - PREP_H - PREP_WC;
        wtrans_body4(Wp, wpt, H_, H_, (id & 63) * 32, (id >> 6) * 32, threadIdx.x, t);
    }
}

// ---------------- TF32 GEMM mainloop: 128x128, BK=32, 3 stages (R14 schedule) ----------------
#define GSTR 36
#define GT_ST (128 * GSTR)
#define G_ST  (2 * GT_ST)
#define GEMM_SMEM (3 * G_ST * 4)    // 110592 B
#define TSSTR 132

#define ISSUE_A(kt, st)                                                           \
    do {                                                                          \
        const float* Asrc = Ab + (kt) * 32;                                       \
        uint32_t au = as_u + (uint32_t)((st) * G_ST * 4);                         \
        _Pragma("unroll")                                                         \
        for (int i = 0; i < 4; i++) {                                             \
            int ch = tid + 256 * i;                                               \
            int r = ch >> 3, c2 = (ch & 7) << 2;                                  \
            cp16(au + (uint32_t)((r * GSTR + c2) * 4), Asrc + (size_t)r * K + c2);\
        }                                                                         \
    } while (0)
#define ISSUE_B(kt, st)                                                           \
    do {                                                                          \
        const float* Bsrc = Bb + (kt) * 32;                                       \
        uint32_t bu = as_u + (uint32_t)((st) * G_ST * 4) + (uint32_t)(GT_ST * 4); \
        _Pragma("unroll")                                                         \
        for (int i = 0; i < 4; i++) {                                             \
            int ch = tid + 256 * i;                                               \
            int r = ch >> 3, c2 = (ch & 7) << 2;                                  \
            cp16(bu + (uint32_t)((r * GSTR + c2) * 4), Bsrc + (size_t)r * K + c2);\
        }                                                                         \
    } while (0)

#define GEMM_MAINLOOP(Aptr, Bptr)                                                 \
    const uint32_t as_u = smem_u32(gsm);                                          \
    const int tid = threadIdx.x;                                                  \
    const int bx = blockIdx.x, by = blockIdx.y;                                   \
    const int warp = tid >> 5, lane = tid & 31;                                   \
    const int wm = (warp & 1) * 64;                                               \
    const int wn = (warp >> 1) * 32;                                              \
    const int lr = lane >> 2;                                                     \
    const int lc = lane & 3;                                                      \
    const int la_m = lane & 15;                                                   \
    const int la_k = (lane >> 4) << 2;                                            \
    const int lb_r = (lane & 7) + ((lane >> 4) << 3);                             \
    const int lb_c = ((lane >> 3) & 1) << 2;                                      \
    const uint32_t a_lane = as_u + (uint32_t)(((wm + la_m) * GSTR + la_k) * 4);   \
    const uint32_t b_lane = as_u + (uint32_t)(GT_ST * 4)                          \
                          + (uint32_t)(((wn + lb_r) * GSTR + lb_c) * 4);          \
    const float* Ab = (Aptr) + (size_t)(by * 128) * K;                            \
    const float* Bb = (Bptr) + (size_t)(bx * 128) * K;                            \
    const int KT = K >> 5;                                                        \
    ISSUE_A(0, 0); ISSUE_B(0, 0); cp_commit();                                    \
    ISSUE_A(1, 1); ISSUE_B(1, 1); cp_commit();                                    \
    float c[4][4][4];                                                             \
    _Pragma("unroll")                                                             \
    for (int mt = 0; mt < 4; mt++)                                                \
        _Pragma("unroll")                                                         \
        for (int nt = 0; nt < 4; nt++)                                            \
            _Pragma("unroll")                                                     \
            for (int j = 0; j < 4; j++) c[mt][nt][j] = 0.f;                       \
    for (int kt = 0; kt < KT; kt++) {                                             \
        cp_wait<1>();                                                             \
        __syncthreads();                                                          \
        const uint32_t stoff = (uint32_t)((kt % 3) * G_ST * 4);                   \
        const uint32_t a_st = a_lane + stoff;                                     \
        const uint32_t b_st = b_lane + stoff;                                     \
        _Pragma("unroll")                                                         \
        for (int ks = 0; ks < 4; ks++) {                                          \
            const int kb = ks * 8;                                                \
            uint32_t af[4][4], bf[4][2];                                          \
            _Pragma("unroll")                                                     \
            for (int mt = 0; mt < 4; mt++)                                        \
                ldsm4(af[mt], a_st + (uint32_t)((mt * 16 * GSTR + kb) * 4));      \
            _Pragma("unroll")                                                     \
            for (int p = 0; p < 2; p++) {                                         \
                uint32_t r[4];                                                    \
                ldsm4(r, b_st + (uint32_t)((p * 16 * GSTR + kb) * 4));            \
                bf[2 * p][0] = r[0]; bf[2 * p][1] = r[1];                         \
                bf[2 * p + 1][0] = r[2]; bf[2 * p + 1][1] = r[3];                 \
            }                                                                     \
            _Pragma("unroll")                                                     \
            for (int mt = 0; mt < 4; mt++)                                        \
                _Pragma("unroll")                                                 \
                for (int nt = 0; nt < 4; nt++)                                    \
                    mma_tf32(c[mt][nt], af[mt], bf[nt]);                          \
            if (ks == 0 && kt + 2 < KT) { ISSUE_A(kt + 2, (kt + 2) % 3); }        \
            if (ks == 1) {                                                        \
                if (kt + 2 < KT) { ISSUE_B(kt + 2, (kt + 2) % 3); }               \
                cp_commit();                                                      \
            }                                                                     \
        }                                                                         \
    }

// ---------------- plain GEMM (proj): C = A @ Bt^T + bias ----------------
__global__ __launch_bounds__(256, 2) void gemm_tf32(
    const float* __restrict__ A, const float* __restrict__ Bt,
    const float* __restrict__ bias, float* __restrict__ C,
    int M, int N, int K)
{
    extern __shared__ float gsm[];
    GEMM_MAINLOOP(A, Bt)

#pragma unroll
    for (int mt = 0; mt < 4; mt++) {
        int row = by * 128 + wm + mt * 16 + lr;
#pragma unroll
        for (int nt = 0; nt < 4; nt++) {
            int col = bx * 128 + wn + nt * 8 + 2 * lc;
            float b0 = bias[col], b1 = bias[col + 1];
            float2 v0 = { c[mt][nt][0] + b0, c[mt][nt][1] + b1 };
            float2 v1 = { c[mt][nt][2] + b0, c[mt][nt][3] + b1 };
            *(float2*)(C + (size_t)row * N + col) = v0;
            *(float2*)(C + (size_t)(row + 8) * N + col) = v1;
        }
    }
}

// ---------------- fused QKV GEMM: rope+logn for Q/K, transpose for V ----------------
__global__ __launch_bounds__(256, 2) void gemm_qkv(
    const float* __restrict__ A, const float* __restrict__ Bt,
    const float* __restrict__ bias,
    const float* __restrict__ cosb, const float* __restrict__ sinb,
    const float* __restrict__ logn,
    float* __restrict__ Qo, float* __restrict__ Ko, float* __restrict__ Vo,
    int M, int N, int K)
{
    extern __shared__ float gsm[];
    GEMM_MAINLOOP(A, Bt)

    __syncthreads();
    float* ts = gsm;                 // [128][TSSTR]
    const bool isV = (bx >= 32);

#pragma unroll
    for (int mt = 0; mt < 4; mt++) {
        int row = wm + mt * 16 + lr;
#pragma unroll
        for (int nt = 0; nt < 4; nt++) {
            int col = wn + nt * 8 + 2 * lc;
            float b0 = bias[bx * 128 + col], b1 = bias[bx * 128 + col + 1];
            float v00 = c[mt][nt][0] + b0, v01 = c[mt][nt][1] + b1;
            float v10 = c[mt][nt][2] + b0, v11 = c[mt][nt][3] + b1;
            if (!isV) {
                ts[row * TSSTR + col] = v00;
                ts[row * TSSTR + col + 1] = v01;
                ts[(row + 8) * TSSTR + col] = v10;
                ts[(row + 8) * TSSTR + col + 1] = v11;
            } else {
                ts[col * TSSTR + row] = v00;
                ts[(col + 1) * TSSTR + row] = v01;
                ts[col * TSSTR + row + 8] = v10;
                ts[(col + 1) * TSSTR + row + 8] = v11;
            }
        }
    }
    __syncthreads();

    if (!isV) {
        const bool isQ = (bx < 16);
        const int h = bx & 15;
        float* dst = isQ ? Qo : Ko;
        for (int t = tid; t < 128 * 32; t += 256) {
            int r = t >> 5, c4 = (t & 31) << 2;
            int sg = by * 128 + r;
            int b = sg >> 11;
            int s = sg & (S_ - 1);
            const float* rowp = ts + r * TSSTR;
            float4 v  = *(const float4*)(rowp + c4);
            int dro = (c4 < 64) ? (c4 + 64) : (c4 - 64);
            float4 vo = *(const float4*)(rowp + dro);
            float4 cv = *(const float4*)(cosb + (size_t)s * HD_ + c4);
            float4 sv = *(const float4*)(sinb + (size_t)s * HD_ + c4);
            float sgn = (c4 < 64) ? -1.f : 1.f;
            float4 res;
            res.x = v.x * cv.x + sgn * vo.x * sv.x;
            res.y = v.y * cv.y + sgn * vo.y * sv.y;
            res.z = v.z * cv.z + sgn * vo.z * sv.z;
            res.w = v.w * cv.w + sgn * vo.w * sv.w;
            if (isQ) {
                float ln = logn[s] * 0.08838834764831845f * 1.4426950408889634f;
                res.x *= ln; res.y *= ln; res.z *= ln; res.w *= ln;
            }
            size_t oidx = (((size_t)(b * NH_ + h) * S_ + s) << 7) + c4;
            uint4 u = { f2tf(res.x), f2tf(res.y), f2tf(res.z), f2tf(res.w) };
            *(uint4*)(dst + oidx) = u;
        }
    } else {
        const int h = bx - 32;
        const int b = by >> 4;
        const int sl0 = (by & 15) * 128;
        for (int t = tid; t < 128 * 32; t += 256) {
            int d = t >> 5, s4 = (t & 31) << 2;
            float4 v = *(const float4*)(ts + d * TSSTR + s4);
            uint4 u = { f2tf(v.x), f2tf(v.y), f2tf(v.z), f2tf(v.w) };
            size_t oidx = ((size_t)((b * NH_ + h) * HD_ + d) * S_) + sl0 + s4;
            *(uint4*)(Vo + oidx) = u;
        }
    }
}

// ---------------- Flash attention v5 (R14) + packed P stores ----------------
#define FBQ 128
#define FBKT 64
#define KSTR 132
#define VSTR 68
#define PSTR 68
#define FK_ST (FBKT * KSTR)
#define FV_ST (HD_ * VSTR)
#define OFF_V (2 * FK_ST)
#define OFF_P (OFF_V + 2 * FV_ST)
#define OFF_AL (OFF_P + FBQ * PSTR)
#define FLASH_SMEM ((OFF_AL + 2 * FBQ) * 4)   // 173056 B

__global__ __launch_bounds__(256) void flash_tc(
    const float* __restrict__ Q, const float* __restrict__ K,
    const float* __restrict__ V, float* __restrict__ ctx)
{
    extern __shared__ float fsm[];
    uint32_t* Ps = (uint32_t*)(fsm + OFF_P);
    float* al_s = fsm + OFF_AL;
    float* l_s  = al_s + FBQ;
    const uint32_t ks_u = smem_u32(fsm);
    const uint32_t vs_u = ks_u + (uint32_t)(OFF_V * 4);
    const uint32_t ps_u = smem_u32(Ps);

    const int qt = (S_ / FBQ - 1) - blockIdx.x;
    const int bh = blockIdx.y;
    const int tid = threadIdx.x;
    const int warp = tid >> 5, lane = tid & 31;
    const int lr = lane >> 2;
    const int lc = lane & 3;

    const int la_m = lane & 15;
    const int la_k = (lane >> 4) << 2;
    const int lb_r = (lane & 7) + ((lane >> 4) << 3);
    const int lb_c = ((lane >> 3) & 1) << 2;

    const int wm2 = (warp & 1) * 64;
    const int wn2 = (warp >> 1) * 32;
    const uint32_t p_lane = ps_u + (uint32_t)(((wm2 + la_m) * PSTR + la_k) * 4);

    const float* Qb = Q + ((size_t)bh * S_ + qt * FBQ) * HD_;
    const float* Kb = K + (size_t)bh * S_ * HD_;
    const float* Vb = V + (size_t)bh * HD_ * S_;

    for (int t = tid; t < FBQ * (HD_ / 4); t += 256) {
        int r = t >> 5, c4 = (t & 31) << 2;
        *(uint4*)(fsm + r * KSTR + c4) = *(const uint4*)(Qb + (size_t)r * HD_ + c4);
    }
    __syncthreads();
    uint32_t qf[16][4];
    {
        const uint32_t q_lane = ks_u + (uint32_t)(((warp * 16 + la_m) * KSTR + la_k) * 4);
#pragma unroll
        for (int ks = 0; ks < 16; ks++)
            ldsm4(qf[ks], q_lane + (uint32_t)(ks * 8 * 4));
    }
    __syncthreads();

    const int nkt = 2 * qt + 2;

#define ISSUE_K_F(kt)                                                             \
    do {                                                                          \
        const float* ksrc = Kb + (size_t)(kt) * FBKT * HD_;                       \
        uint32_t kdst = ks_u + (uint32_t)(((kt) & 1) * FK_ST * 4);                \
        _Pragma("unroll")                                                         \
        for (int i = 0; i < 8; i++) {                                             \
            int ch = tid + 256 * i;                                               \
            int kr = ch >> 5, kc = (ch & 31) << 2;                                \
            cp16(kdst + (uint32_t)((kr * KSTR + kc) * 4),                         \
                 ksrc + (size_t)kr * HD_ + kc);                                   \
        }                                                                         \
    } while (0)
#define ISSUE_V_F(kt)                                                             \
    do {                                                                          \
        const float* vsrc = Vb + (size_t)(kt) * FBKT;                             \
        uint32_t vdst = vs_u + (uint32_t)(((kt) & 1) * FV_ST * 4);                \
        _Pragma("unroll")                                                         \
        for (int i = 0; i < 8; i++) {                                             \
            int ch = tid + 256 * i;                                               \
            int vr = ch >> 4, vc = (ch & 15) << 2;                                \
            cp16(vdst + (uint32_t)((vr * VSTR + vc) * 4),                         \
                 vsrc + (size_t)vr * S_ + vc);                                    \
        }                                                                         \
    } while (0)

    ISSUE_K_F(0);
    ISSUE_V_F(0);
    cp_commit();

    float m0 = -1e30f, m1 = -1e30f;
    float l0 = 0.f, l1 = 0.f;
    float o[4][4][4];
#pragma unroll
    for (int mt = 0; mt < 4; mt++)
#pragma unroll
        for (int nt = 0; nt < 4; nt++)
#pragma unroll
            for (int j = 0; j < 4; j++) o[mt][nt][j] = 0.f;

    const int r0 = warp * 16 + lr;
    const int g0 = qt * FBQ + r0;
    const int g1 = g0 + 8;

    for (int kt = 0; kt < nkt; kt++) {
        cp_wait<0>();                      // KV(kt) resident
        __syncthreads();                   // + all PV(kt-1) reads finished

        const bool pre = (kt + 1 < nkt);
        if (pre) { ISSUE_K_F(kt + 1); }

        const uint32_t kst_u = ks_u + (uint32_t)((kt & 1) * FK_ST * 4);
        const uint32_t vst_u = vs_u + (uint32_t)((kt & 1) * FV_ST * 4);
        const uint32_t k_lane = kst_u + (uint32_t)((lb_r * KSTR + lb_c) * 4);

        float s[8][4];
#pragma unroll
        for (int nt = 0; nt < 8; nt++)
#pragma unroll
            for (int j = 0; j < 4; j++) s[nt][j] = 0.f;

        uint32_t kf[2][4][4];
#pragma unroll
        for (int p = 0; p < 4; p++)
            ldsm4(kf[0][p], k_lane + (uint32_t)((p * 16 * KSTR) * 4));
#pragma unroll
        for (int ksx = 0; ksx < 16; ksx++) {
            const int cur = ksx & 1;
            if (ksx < 15) {
                const int kbn = (ksx + 1) * 8;
#pragma unroll
                for (int p = 0; p < 4; p++)
                    ldsm4(kf[cur ^ 1][p], k_lane + (uint32_t)((p * 16 * KSTR + kbn) * 4));
            }
#pragma unroll
            for (int p = 0; p < 4; p++) {
                mma_tf32(s[2 * p], qf[ksx], kf[cur][p]);
                mma_tf32(s[2 * p + 1], qf[ksx], kf[cur][p] + 2);
            }
            if (ksx == 0) {
                if (pre) { ISSUE_V_F(kt + 1); }
                cp_commit();
            }
        }

        if (kt * FBKT + FBKT - 1 > qt * FBQ + warp * 16) {
#pragma unroll
            for (int nt = 0; nt < 8; nt++) {
                int colb = kt * FBKT + nt * 8 + 2 * lc;
                if (colb > g0)     s[nt][0] = -1e30f;
                if (colb + 1 > g0) s[nt][1] = -1e30f;
                if (colb > g1)     s[nt][2] = -1e30f;
                if (colb + 1 > g1) s[nt][3] = -1e30f;
            }
        }

        float mx0 = -1e30f, mx1 = -1e30f;
#pragma unroll
        for (int nt = 0; nt < 8; nt++) {
            mx0 = fmaxf(mx0, fmaxf(s[nt][0], s[nt][1]));
            mx1 = fmaxf(mx1, fmaxf(s[nt][2], s[nt][3]));
        }
        mx0 = fmaxf(mx0, __shfl_xor_sync(0xffffffffu, mx0, 1));
        mx0 = fmaxf(mx0, __shfl_xor_sync(0xffffffffu, mx0, 2));
        mx1 = fmaxf(mx1, __shfl_xor_sync(0xffffffffu, mx1, 1));
        mx1 = fmaxf(mx1, __shfl_xor_sync(0xffffffffu, mx1, 2));

        float nm0 = fmaxf(m0, mx0), nm1 = fmaxf(m1, mx1);
        float al0 = exp2f(m0 - nm0), al1 = exp2f(m1 - nm1);
        m0 = nm0; m1 = nm1;

        float sum0 = 0.f, sum1 = 0.f;
#pragma unroll
        for (int nt = 0; nt < 8; nt++) {
            s[nt][0] = exp2f(s[nt][0] - nm0);
            s[nt][1] = exp2f(s[nt][1] - nm0);
            s[nt][2] = exp2f(s[nt][2] - nm1);
            s[nt][3] = exp2f(s[nt][3] - nm1);
            sum0 += s[nt][0] + s[nt][1];
            sum1 += s[nt][2] + s[nt][3];
        }
        sum0 += __shfl_xor_sync(0xffffffffu, sum0, 1);
        sum0 += __shfl_xor_sync(0xffffffffu, sum0, 2);
        sum1 += __shfl_xor_sync(0xffffffffu, sum1, 1);
        sum1 += __shfl_xor_sync(0xffffffffu, sum1, 2);
        l0 = l0 * al0 + sum0;
        l1 = l1 * al1 + sum1;

        if (lc == 0) {
            al_s[r0] = al0;
            al_s[r0 + 8] = al1;
        }

        // ---- store P (tf32) as 64-bit pairs ----
#pragma unroll
        for (int nt = 0; nt < 8; nt++) {
            int colp = nt * 8 + 2 * lc;
            uint2 p0 = { f2tf(s[nt][0]), f2tf(s[nt][1]) };
            uint2 p1 = { f2tf(s[nt][2]), f2tf(s[nt][3]) };
            *(uint2*)&Ps[r0 * PSTR + colp]       = p0;
            *(uint2*)&Ps[(r0 + 8) * PSTR + colp] = p1;
        }
        __syncthreads();                   // publish P + al

#pragma unroll
        for (int mt = 0; mt < 4; mt++) {
            float a0 = al_s[wm2 + mt * 16 + lr];
            float a1 = al_s[wm2 + mt * 16 + lr + 8];
#pragma unroll
            for (int nt = 0; nt < 4; nt++) {
                o[mt][nt][0] *= a0; o[mt][nt][1] *= a0;
                o[mt][nt][2] *= a1; o[mt][nt][3] *= a1;
            }
        }

        const uint32_t v_lane = vst_u + (uint32_t)(((wn2 + lb_r) * VSTR + lb_c) * 4);
        uint32_t pa[2][4][4], pb[2][2][4];
#pragma unroll
        for (int mt = 0; mt < 4; mt++)
            ldsm4(pa[0][mt], p_lane + (uint32_t)((mt * 16 * PSTR) * 4));
#pragma unroll
        for (int p = 0; p < 2; p++)
            ldsm4(pb[0][p], v_lane + (uint32_t)((p * 16 * VSTR) * 4));

#pragma unroll
        for (int ksx = 0; ksx < 8; ksx++) {
            const int cur = ksx & 1;
            if (ksx < 7) {
                const int kbn = (ksx + 1) * 8;
#pragma unroll
                for (int mt = 0; mt < 4; mt++)
                    ldsm4(pa[cur ^ 1][mt], p_lane + (uint32_t)((mt * 16 * PSTR + kbn) * 4));
#pragma unroll
                for (int p = 0; p < 2; p++)
                    ldsm4(pb[cur ^ 1][p], v_lane + (uint32_t)((p * 16 * VSTR + kbn) * 4));
            }
#pragma unroll
            for (int mt = 0; mt < 4; mt++) {
                mma_tf32(o[mt][0], pa[cur][mt], pb[cur][0]);
                mma_tf32(o[mt][1], pa[cur][mt], pb[cur][0] + 2);
                mma_tf32(o[mt][2], pa[cur][mt], pb[cur][1]);
                mma_tf32(o[mt][3], pa[cur][mt], pb[cur][1] + 2);
            }
        }
        // no end barrier: next iteration's top barrier protects stage reuse
    }
#undef ISSUE_K_F
#undef ISSUE_V_F

    if (lc == 0) {
        l_s[r0] = l0;
        l_s[r0 + 8] = l1;
    }
    __syncthreads();

    const int b = bh >> 4, h = bh & 15;
#pragma unroll
    for (int mt = 0; mt < 4; mt++) {
        int rloc = wm2 + mt * 16 + lr;
        int row0 = qt * FBQ + rloc;
        float il0 = 1.f / l_s[rloc];
        float il1 = 1.f / l_s[rloc + 8];
        float* out0 = ctx + (size_t)(b * S_ + row0) * H_ + h * HD_ + wn2;
        float* out1 = out0 + (size_t)8 * H_;
#pragma unroll
        for (int nt = 0; nt < 4; nt++) {
            int col = nt * 8 + 2 * lc;
            float2 v0 = { f2tff(o[mt][nt][0] * il0), f2tff(o[mt][nt][1] * il0) };
            float2 v1 = { f2tff(o[mt][nt][2] * il1), f2tff(o[mt][nt][3] * il1) };
            *(float2*)(out0 + col) = v0;
            *(float2*)(out1 + col) = v1;
        }
    }
}

// ---------------- launch ----------------
extern "C" void kernel_launch(void* const* d_in, const int* in_sizes, int n_in,
                              void* d_out, int out_size)
{
    const float* hidden = (const float*)d_in[0];
    const float* cosb   = (const float*)d_in[1];
    const float* sinb   = (const float*)d_in[2];
    // d_in[3]: attention_mask (pure causal -> implemented directly)
    const float* logn   = (const float*)d_in[4];
    const float* Wc     = (const float*)d_in[5];
    const float* bc     = (const float*)d_in[6];
    const float* Wp     = (const float*)d_in[7];
    const float* bp     = (const float*)d_in[8];
    float* out = (float*)d_out;

    float *Q, *Kt, *Vt, *ctx, *hid_tf, *wct, *wpt;
    cudaGetSymbolAddress((void**)&Q,      g_q);
    cudaGetSymbolAddress((void**)&Kt,     g_k);
    cudaGetSymbolAddress((void**)&Vt,     g_v);
    cudaGetSymbolAddress((void**)&ctx,    g_ctx);
    cudaGetSymbolAddress((void**)&hid_tf, g_hid_tf);
    cudaGetSymbolAddress((void**)&wct,    g_wct);
    cudaGetSymbolAddress((void**)&wpt,    g_wpt);

    cudaFuncSetAttribute(gemm_tf32,
                         cudaFuncAttributeMaxDynamicSharedMemorySize, GEMM_SMEM);
    cudaFuncSetAttribute(gemm_qkv,
                         cudaFuncAttributeMaxDynamicSharedMemorySize, GEMM_SMEM);
    cudaFuncSetAttribute(flash_tc,
                         cudaFuncAttributeMaxDynamicSharedMemorySize, FLASH_SMEM);

    // 0) pre-round A + transpose/round weights (one launch)
    prep_all<<<PREP_H + PREP_WC + PREP_WP, 256>>>(hidden, Wc, Wp, hid_tf, wct, wpt);

    // 1) fused QKV GEMM + rope/logn/V-transpose -> g_q, g_k, g_v
    gemm_qkv<<<dim3(QKV_N / 128, ROWS_ / 128), 256, GEMM_SMEM>>>(
        hid_tf, wct, bc, cosb, sinb, logn, Q, Kt, Vt, ROWS_, QKV_N, H_);

    // 2) flash attention -> ctx [4096, 2048]
    flash_tc<<<dim3(S_ / FBQ, B_ * NH_), 256, FLASH_SMEM>>>(Q, Kt, Vt, ctx);

    // 3) out = ctx @ Wp + bp      [4096,2048]
    gemm_tf32<<<dim3(H_ / 128, ROWS_ / 128), 256, GEMM_SMEM>>>(
        ctx, wpt, bp, out, ROWS_, H_, H_);
}

// round 17
// speedup vs baseline: 1.0128x; 1.0057x over previous
#include <cuda_runtime.h>
#include <cuda_bf16.h>
#include <math.h>
#include <stdint.h>

// Problem constants
#define B_  2
#define S_  2048
#define H_  2048
#define NH_ 16
#define HD_ 128
#define ROWS_ (B_ * S_)        // 4096
#define QKV_N (3 * H_)         // 6144

// ---------------- scratch (static device globals; no allocation) ----------------
__device__ float g_q[(size_t)B_ * NH_ * S_ * HD_];        // [b,h,s,d] tf32-rounded (log2e folded)
__device__ float g_k[(size_t)B_ * NH_ * S_ * HD_];        // [b,h,s,d] tf32-rounded
__device__ float g_v[(size_t)B_ * NH_ * S_ * HD_];        // [b,h,d,s] tf32-rounded
__device__ float g_ctx[(size_t)ROWS_ * H_];               // [b*s, h*d] tf32-rounded
__device__ float g_hid_tf[(size_t)ROWS_ * H_];            // tf32-rounded A
__device__ float g_wct[(size_t)QKV_N * H_];               // Wc^T [6144][2048] tf32
__device__ float g_wpt[(size_t)H_ * H_];                  // Wp^T [2048][2048] tf32

// ---------------- helpers ----------------
__device__ __forceinline__ uint32_t f2tf(float x) {
    uint32_t r;
    asm("cvt.rna.tf32.f32 %0, %1;" : "=r"(r) : "f"(x));
    return r;
}
__device__ __forceinline__ float f2tff(float x) { return __uint_as_float(f2tf(x)); }

__device__ __forceinline__ float ex2(float x) {
    float r;
    asm("ex2.approx.ftz.f32 %0, %1;" : "=f"(r) : "f"(x));
    return r;
}

__device__ __forceinline__ void mma_tf32(float* c, const uint32_t* a, const uint32_t* b) {
    asm volatile(
        "mma.sync.aligned.m16n8k8.row.col.f32.tf32.tf32.f32 "
        "{%0,%1,%2,%3}, {%4,%5,%6,%7}, {%8,%9}, {%0,%1,%2,%3};\n"
        : "+f"(c[0]), "+f"(c[1]), "+f"(c[2]), "+f"(c[3])
        : "r"(a[0]), "r"(a[1]), "r"(a[2]), "r"(a[3]),
          "r"(b[0]), "r"(b[1]));
}
__device__ __forceinline__ void ldsm4(uint32_t* r, uint32_t addr) {
    asm volatile("ldmatrix.sync.aligned.m8n8.x4.shared.b16 {%0,%1,%2,%3}, [%4];"
        : "=r"(r[0]), "=r"(r[1]), "=r"(r[2]), "=r"(r[3]) : "r"(addr));
}
__device__ __forceinline__ uint32_t smem_u32(const void* p) {
    return (uint32_t)__cvta_generic_to_shared(p);
}
__device__ __forceinline__ void cp16(uint32_t dst, const void* src) {
    asm volatile("cp.async.cg.shared.global [%0], [%1], 16;" :: "r"(dst), "l"(src));
}
__device__ __forceinline__ void cp_commit() {
    asm volatile("cp.async.commit_group;");
}
template<int N> __device__ __forceinline__ void cp_wait() {
    asm volatile("cp.async.wait_group %0;" :: "n"(N));
}

// ---------------- merged preprocessing (float4 transposes) ----------------
__device__ __forceinline__ void wtrans_body4(
    const float* __restrict__ in, float* __restrict__ out,
    int K, int N, int k0, int n0, int tid, float (*t)[33])
{
    const int x4 = tid & 7, y = tid >> 3;
    {
        float4 v = *(const float4*)(in + (size_t)(k0 + y) * N + n0 + x4 * 4);
        t[y][x4 * 4 + 0] = v.x;
        t[y][x4 * 4 + 1] = v.y;
        t[y][x4 * 4 + 2] = v.z;
        t[y][x4 * 4 + 3] = v.w;
    }
    __syncthreads();
    {
        float4 v;
        v.x = f2tff(t[x4 * 4 + 0][y]);
        v.y = f2tff(t[x4 * 4 + 1][y]);
        v.z = f2tff(t[x4 * 4 + 2][y]);
        v.w = f2tff(t[x4 * 4 + 3][y]);
        *(float4*)(out + (size_t)(n0 + y) * K + k0 + x4 * 4) = v;
    }
}

#define PREP_H 8192
#define PREP_WC 12288
#define PREP_WP 4096

__global__ __launch_bounds__(256) void prep_all(
    const float* __restrict__ hidden, const float* __restrict__ Wc,
    const float* __restrict__ Wp,
    float* __restrict__ hid_tf, float* __restrict__ wct, float* __restrict__ wpt)
{
    __shared__ float t[32][33];
    const int bid = blockIdx.x;
    if (bid < PREP_H) {
        int i = bid * 256 + threadIdx.x;
        float4 v = ((const float4*)hidden)[i];
        v.x = f2tff(v.x); v.y = f2tff(v.y); v.z = f2tff(v.z); v.w = f2tff(v.w);
        ((float4*)hid_tf)[i] = v;
    } else if (bid < PREP_H + PREP_WC) {
        int id = bid - PREP_H;
        wtrans_body4(Wc, wct, H_, QKV_N, (id & 63) * 32, (id >> 6) * 32, threadIdx.x, t);
    } else {
        int id = bid - PREP_H - PREP_WC;
        wtrans_body4(Wp, wpt, H_, H_, (id & 63) * 32, (id >> 6) * 32, threadIdx.x, t);
    }
}

// ---------------- TF32 GEMM mainloop: 128x128, BK=32, 3 stages (R14 schedule) ----------------
#define GSTR 36
#define GT_ST (128 * GSTR)
#define G_ST  (2 * GT_ST)
#define GEMM_SMEM (3 * G_ST * 4)    // 110592 B
#define TSSTR 132

#define ISSUE_A(kt, st)                                                           \
    do {                                                                          \
        const float* Asrc = Ab + (kt) * 32;                                       \
        uint32_t au = as_u + (uint32_t)((st) * G_ST * 4);                         \
        _Pragma("unroll")                                                         \
        for (int i = 0; i < 4; i++) {                                             \
            int ch = tid + 256 * i;                                               \
            int r = ch >> 3, c2 = (ch & 7) << 2;                                  \
            cp16(au + (uint32_t)((r * GSTR + c2) * 4), Asrc + (size_t)r * K + c2);\
        }                                                                         \
    } while (0)
#define ISSUE_B(kt, st)                                                           \
    do {                                                                          \
        const float* Bsrc = Bb + (kt) * 32;                                       \
        uint32_t bu = as_u + (uint32_t)((st) * G_ST * 4) + (uint32_t)(GT_ST * 4); \
        _Pragma("unroll")                                                         \
        for (int i = 0; i < 4; i++) {                                             \
            int ch = tid + 256 * i;                                               \
            int r = ch >> 3, c2 = (ch & 7) << 2;                                  \
            cp16(bu + (uint32_t)((r * GSTR + c2) * 4), Bsrc + (size_t)r * K + c2);\
        }                                                                         \
    } while (0)

#define GEMM_MAINLOOP(Aptr, Bptr)                                                 \
    const uint32_t as_u = smem_u32(gsm);                                          \
    const int tid = threadIdx.x;                                                  \
    const int bx = blockIdx.x, by = blockIdx.y;                                   \
    const int warp = tid >> 5, lane = tid & 31;                                   \
    const int wm = (warp & 1) * 64;                                               \
    const int wn = (warp >> 1) * 32;                                              \
    const int lr = lane >> 2;                                                     \
    const int lc = lane & 3;                                                      \
    const int la_m = lane & 15;                                                   \
    const int la_k = (lane >> 4) << 2;                                            \
    const int lb_r = (lane & 7) + ((lane >> 4) << 3);                             \
    const int lb_c = ((lane >> 3) & 1) << 2;                                      \
    const uint32_t a_lane = as_u + (uint32_t)(((wm + la_m) * GSTR + la_k) * 4);   \
    const uint32_t b_lane = as_u + (uint32_t)(GT_ST * 4)                          \
                          + (uint32_t)(((wn + lb_r) * GSTR + lb_c) * 4);          \
    const float* Ab = (Aptr) + (size_t)(by * 128) * K;                            \
    const float* Bb = (Bptr) + (size_t)(bx * 128) * K;                            \
    const int KT = K >> 5;                                                        \
    ISSUE_A(0, 0); ISSUE_B(0, 0); cp_commit();                                    \
    ISSUE_A(1, 1); ISSUE_B(1, 1); cp_commit();                                    \
    float c[4][4][4];                                                             \
    _Pragma("unroll")                                                             \
    for (int mt = 0; mt < 4; mt++)                                                \
        _Pragma("unroll")                                                         \
        for (int nt = 0; nt < 4; nt++)                                            \
            _Pragma("unroll")                                                     \
            for (int j = 0; j < 4; j++) c[mt][nt][j] = 0.f;                       \
    for (int kt = 0; kt < KT; kt++) {                                             \
        cp_wait<1>();                                                             \
        __syncthreads();                                                          \
        const uint32_t stoff = (uint32_t)((kt % 3) * G_ST * 4);                   \
        const uint32_t a_st = a_lane + stoff;                                     \
        const uint32_t b_st = b_lane + stoff;                                     \
        _Pragma("unroll")                                                         \
        for (int ks = 0; ks < 4; ks++) {                                          \
            const int kb = ks * 8;                                                \
            uint32_t af[4][4], bf[4][2];                                          \
            _Pragma("unroll")                                                     \
            for (int mt = 0; mt < 4; mt++)                                        \
                ldsm4(af[mt], a_st + (uint32_t)((mt * 16 * GSTR + kb) * 4));      \
            _Pragma("unroll")                                                     \
            for (int p = 0; p < 2; p++) {                                         \
                uint32_t r[4];                                                    \
                ldsm4(r, b_st + (uint32_t)((p * 16 * GSTR + kb) * 4));            \
                bf[2 * p][0] = r[0]; bf[2 * p][1] = r[1];                         \
                bf[2 * p + 1][0] = r[2]; bf[2 * p + 1][1] = r[3];                 \
            }                                                                     \
            _Pragma("unroll")                                                     \
            for (int mt = 0; mt < 4; mt++)                                        \
                _Pragma("unroll")                                                 \
                for (int nt = 0; nt < 4; nt++)                                    \
                    mma_tf32(c[mt][nt], af[mt], bf[nt]);                          \
            if (ks == 0 && kt + 2 < KT) { ISSUE_A(kt + 2, (kt + 2) % 3); }        \
            if (ks == 1) {                                                        \
                if (kt + 2 < KT) { ISSUE_B(kt + 2, (kt + 2) % 3); }               \
                cp_commit();                                                      \
            }                                                                     \
        }                                                                         \
    }

// ---------------- plain GEMM (proj): C = A @ Bt^T + bias ----------------
__global__ __launch_bounds__(256, 2) void gemm_tf32(
    const float* __restrict__ A, const float* __restrict__ Bt,
    const float* __restrict__ bias, float* __restrict__ C,
    int M, int N, int K)
{
    extern __shared__ float gsm[];
    GEMM_MAINLOOP(A, Bt)

#pragma unroll
    for (int mt = 0; mt < 4; mt++) {
        int row = by * 128 + wm + mt * 16 + lr;
#pragma unroll
        for (int nt = 0; nt < 4; nt++) {
            int col = bx * 128 + wn + nt * 8 + 2 * lc;
            float b0 = bias[col], b1 = bias[col + 1];
            float2 v0 = { c[mt][nt][0] + b0, c[mt][nt][1] + b1 };
            float2 v1 = { c[mt][nt][2] + b0, c[mt][nt][3] + b1 };
            *(float2*)(C + (size_t)row * N + col) = v0;
            *(float2*)(C + (size_t)(row + 8) * N + col) = v1;
        }
    }
}

// ---------------- fused QKV GEMM: rope+logn for Q/K, transpose for V ----------------
__global__ __launch_bounds__(256, 2) void gemm_qkv(
    const float* __restrict__ A, const float* __restrict__ Bt,
    const float* __restrict__ bias,
    const float* __restrict__ cosb, const float* __restrict__ sinb,
    const float* __restrict__ logn,
    float* __restrict__ Qo, float* __restrict__ Ko, float* __restrict__ Vo,
    int M, int N, int K)
{
    extern __shared__ float gsm[];
    GEMM_MAINLOOP(A, Bt)

    __syncthreads();
    float* ts = gsm;                 // [128][TSSTR]
    const bool isV = (bx >= 32);

#pragma unroll
    for (int mt = 0; mt < 4; mt++) {
        int row = wm + mt * 16 + lr;
#pragma unroll
        for (int nt = 0; nt < 4; nt++) {
            int col = wn + nt * 8 + 2 * lc;
            float b0 = bias[bx * 128 + col], b1 = bias[bx * 128 + col + 1];
            float v00 = c[mt][nt][0] + b0, v01 = c[mt][nt][1] + b1;
            float v10 = c[mt][nt][2] + b0, v11 = c[mt][nt][3] + b1;
            if (!isV) {
                ts[row * TSSTR + col] = v00;
                ts[row * TSSTR + col + 1] = v01;
                ts[(row + 8) * TSSTR + col] = v10;
                ts[(row + 8) * TSSTR + col + 1] = v11;
            } else {
                ts[col * TSSTR + row] = v00;
                ts[(col + 1) * TSSTR + row] = v01;
                ts[col * TSSTR + row + 8] = v10;
                ts[(col + 1) * TSSTR + row + 8] = v11;
            }
        }
    }
    __syncthreads();

    if (!isV) {
        const bool isQ = (bx < 16);
        const int h = bx & 15;
        float* dst = isQ ? Qo : Ko;
        for (int t = tid; t < 128 * 32; t += 256) {
            int r = t >> 5, c4 = (t & 31) << 2;
            int sg = by * 128 + r;
            int b = sg >> 11;
            int s = sg & (S_ - 1);
            const float* rowp = ts + r * TSSTR;
            float4 v  = *(const float4*)(rowp + c4);
            int dro = (c4 < 64) ? (c4 + 64) : (c4 - 64);
            float4 vo = *(const float4*)(rowp + dro);
            float4 cv = *(const float4*)(cosb + (size_t)s * HD_ + c4);
            float4 sv = *(const float4*)(sinb + (size_t)s * HD_ + c4);
            float sgn = (c4 < 64) ? -1.f : 1.f;
            float4 res;
            res.x = v.x * cv.x + sgn * vo.x * sv.x;
            res.y = v.y * cv.y + sgn * vo.y * sv.y;
            res.z = v.z * cv.z + sgn * vo.z * sv.z;
            res.w = v.w * cv.w + sgn * vo.w * sv.w;
            if (isQ) {
                float ln = logn[s] * 0.08838834764831845f * 1.4426950408889634f;
                res.x *= ln; res.y *= ln; res.z *= ln; res.w *= ln;
            }
            size_t oidx = (((size_t)(b * NH_ + h) * S_ + s) << 7) + c4;
            uint4 u = { f2tf(res.x), f2tf(res.y), f2tf(res.z), f2tf(res.w) };
            *(uint4*)(dst + oidx) = u;
        }
    } else {
        const int h = bx - 32;
        const int b = by >> 4;
        const int sl0 = (by & 15) * 128;
        for (int t = tid; t < 128 * 32; t += 256) {
            int d = t >> 5, s4 = (t & 31) << 2;
            float4 v = *(const float4*)(ts + d * TSSTR + s4);
            uint4 u = { f2tf(v.x), f2tf(v.y), f2tf(v.z), f2tf(v.w) };
            size_t oidx = ((size_t)((b * NH_ + h) * HD_ + d) * S_) + sl0 + s4;
            *(uint4*)(Vo + oidx) = u;
        }
    }
}

// ---------------- Flash attention (R16) + ex2.approx softmax ----------------
#define FBQ 128
#define FBKT 64
#define KSTR 132
#define VSTR 68
#define PSTR 68
#define FK_ST (FBKT * KSTR)
#define FV_ST (HD_ * VSTR)
#define OFF_V (2 * FK_ST)
#define OFF_P (OFF_V + 2 * FV_ST)
#define OFF_AL (OFF_P + FBQ * PSTR)
#define FLASH_SMEM ((OFF_AL + 2 * FBQ) * 4)   // 173056 B

__global__ __launch_bounds__(256) void flash_tc(
    const float* __restrict__ Q, const float* __restrict__ K,
    const float* __restrict__ V, float* __restrict__ ctx)
{
    extern __shared__ float fsm[];
    uint32_t* Ps = (uint32_t*)(fsm + OFF_P);
    float* al_s = fsm + OFF_AL;
    float* l_s  = al_s + FBQ;
    const uint32_t ks_u = smem_u32(fsm);
    const uint32_t vs_u = ks_u + (uint32_t)(OFF_V * 4);
    const uint32_t ps_u = smem_u32(Ps);

    const int qt = (S_ / FBQ - 1) - blockIdx.x;
    const int bh = blockIdx.y;
    const int tid = threadIdx.x;
    const int warp = tid >> 5, lane = tid & 31;
    const int lr = lane >> 2;
    const int lc = lane & 3;

    const int la_m = lane & 15;
    const int la_k = (lane >> 4) << 2;
    const int lb_r = (lane & 7) + ((lane >> 4) << 3);
    const int lb_c = ((lane >> 3) & 1) << 2;

    const int wm2 = (warp & 1) * 64;
    const int wn2 = (warp >> 1) * 32;
    const uint32_t p_lane = ps_u + (uint32_t)(((wm2 + la_m) * PSTR + la_k) * 4);

    const float* Qb = Q + ((size_t)bh * S_ + qt * FBQ) * HD_;
    const float* Kb = K + (size_t)bh * S_ * HD_;
    const float* Vb = V + (size_t)bh * HD_ * S_;

    for (int t = tid; t < FBQ * (HD_ / 4); t += 256) {
        int r = t >> 5, c4 = (t & 31) << 2;
        *(uint4*)(fsm + r * KSTR + c4) = *(const uint4*)(Qb + (size_t)r * HD_ + c4);
    }
    __syncthreads();
    uint32_t qf[16][4];
    {
        const uint32_t q_lane = ks_u + (uint32_t)(((warp * 16 + la_m) * KSTR + la_k) * 4);
#pragma unroll
        for (int ks = 0; ks < 16; ks++)
            ldsm4(qf[ks], q_lane + (uint32_t)(ks * 8 * 4));
    }
    __syncthreads();

    const int nkt = 2 * qt + 2;

#define ISSUE_K_F(kt)                                                             \
    do {                                                                          \
        const float* ksrc = Kb + (size_t)(kt) * FBKT * HD_;                       \
        uint32_t kdst = ks_u + (uint32_t)(((kt) & 1) * FK_ST * 4);                \
        _Pragma("unroll")                                                         \
        for (int i = 0; i < 8; i++) {                                             \
            int ch = tid + 256 * i;                                               \
            int kr = ch >> 5, kc = (ch & 31) << 2;                                \
            cp16(kdst + (uint32_t)((kr * KSTR + kc) * 4),                         \
                 ksrc + (size_t)kr * HD_ + kc);                                   \
        }                                                                         \
    } while (0)
#define ISSUE_V_F(kt)                                                             \
    do {                                                                          \
        const float* vsrc = Vb + (size_t)(kt) * FBKT;                             \
        uint32_t vdst = vs_u + (uint32_t)(((kt) & 1) * FV_ST * 4);                \
        _Pragma("unroll")                                                         \
        for (int i = 0; i < 8; i++) {                                             \
            int ch = tid + 256 * i;                                               \
            int vr = ch >> 4, vc = (ch & 15) << 2;                                \
            cp16(vdst + (uint32_t)((vr * VSTR + vc) * 4),                         \
                 vsrc + (size_t)vr * S_ + vc);                                    \
        }                                                                         \
    } while (0)

    ISSUE_K_F(0);
    ISSUE_V_F(0);
    cp_commit();

    float m0 = -1e30f, m1 = -1e30f;
    float l0 = 0.f, l1 = 0.f;
    float o[4][4][4];
#pragma unroll
    for (int mt = 0; mt < 4; mt++)
#pragma unroll
        for (int nt = 0; nt < 4; nt++)
#pragma unroll
            for (int j = 0; j < 4; j++) o[mt][nt][j] = 0.f;

    const int r0 = warp * 16 + lr;
    const int g0 = qt * FBQ + r0;
    const int g1 = g0 + 8;

    for (int kt = 0; kt < nkt; kt++) {
        cp_wait<0>();                      // KV(kt) resident
        __syncthreads();                   // + all PV(kt-1) reads finished

        const bool pre = (kt + 1 < nkt);
        if (pre) { ISSUE_K_F(kt + 1); }

        const uint32_t kst_u = ks_u + (uint32_t)((kt & 1) * FK_ST * 4);
        const uint32_t vst_u = vs_u + (uint32_t)((kt & 1) * FV_ST * 4);
        const uint32_t k_lane = kst_u + (uint32_t)((lb_r * KSTR + lb_c) * 4);

        float s[8][4];
#pragma unroll
        for (int nt = 0; nt < 8; nt++)
#pragma unroll
            for (int j = 0; j < 4; j++) s[nt][j] = 0.f;

        uint32_t kf[2][4][4];
#pragma unroll
        for (int p = 0; p < 4; p++)
            ldsm4(kf[0][p], k_lane + (uint32_t)((p * 16 * KSTR) * 4));
#pragma unroll
        for (int ksx = 0; ksx < 16; ksx++) {
            const int cur = ksx & 1;
            if (ksx < 15) {
                const int kbn = (ksx + 1) * 8;
#pragma unroll
                for (int p = 0; p < 4; p++)
                    ldsm4(kf[cur ^ 1][p], k_lane + (uint32_t)((p * 16 * KSTR + kbn) * 4));
            }
#pragma unroll
            for (int p = 0; p < 4; p++) {
                mma_tf32(s[2 * p], qf[ksx], kf[cur][p]);
                mma_tf32(s[2 * p + 1], qf[ksx], kf[cur][p] + 2);
            }
            if (ksx == 0) {
                if (pre) { ISSUE_V_F(kt + 1); }
                cp_commit();
            }
        }

        if (kt * FBKT + FBKT - 1 > qt * FBQ + warp * 16) {
#pragma unroll
            for (int nt = 0; nt < 8; nt++) {
                int colb = kt * FBKT + nt * 8 + 2 * lc;
                if (colb > g0)     s[nt][0] = -1e30f;
                if (colb + 1 > g0) s[nt][1] = -1e30f;
                if (colb > g1)     s[nt][2] = -1e30f;
                if (colb + 1 > g1) s[nt][3] = -1e30f;
            }
        }

        float mx0 = -1e30f, mx1 = -1e30f;
#pragma unroll
        for (int nt = 0; nt < 8; nt++) {
            mx0 = fmaxf(mx0, fmaxf(s[nt][0], s[nt][1]));
            mx1 = fmaxf(mx1, fmaxf(s[nt][2], s[nt][3]));
        }
        mx0 = fmaxf(mx0, __shfl_xor_sync(0xffffffffu, mx0, 1));
        mx0 = fmaxf(mx0, __shfl_xor_sync(0xffffffffu, mx0, 2));
        mx1 = fmaxf(mx1, __shfl_xor_sync(0xffffffffu, mx1, 1));
        mx1 = fmaxf(mx1, __shfl_xor_sync(0xffffffffu, mx1, 2));

        float nm0 = fmaxf(m0, mx0), nm1 = fmaxf(m1, mx1);
        float al0 = ex2(m0 - nm0), al1 = ex2(m1 - nm1);
        m0 = nm0; m1 = nm1;

        float sum0 = 0.f, sum1 = 0.f;
#pragma unroll
        for (int nt = 0; nt < 8; nt++) {
            s[nt][0] = ex2(s[nt][0] - nm0);
            s[nt][1] = ex2(s[nt][1] - nm0);
            s[nt][2] = ex2(s[nt][2] - nm1);
            s[nt][3] = ex2(s[nt][3] - nm1);
            sum0 += s[nt][0] + s[nt][1];
            sum1 += s[nt][2] + s[nt][3];
        }
        sum0 += __shfl_xor_sync(0xffffffffu, sum0, 1);
        sum0 += __shfl_xor_sync(0xffffffffu, sum0, 2);
        sum1 += __shfl_xor_sync(0xffffffffu, sum1, 1);
        sum1 += __shfl_xor_sync(0xffffffffu, sum1, 2);
        l0 = l0 * al0 + sum0;
        l1 = l1 * al1 + sum1;

        if (lc == 0) {
            al_s[r0] = al0;
            al_s[r0 + 8] = al1;
        }

        // ---- store P (tf32) as 64-bit pairs ----
#pragma unroll
        for (int nt = 0; nt < 8; nt++) {
            int colp = nt * 8 + 2 * lc;
            uint2 p0 = { f2tf(s[nt][0]), f2tf(s[nt][1]) };
            uint2 p1 = { f2tf(s[nt][2]), f2tf(s[nt][3]) };
            *(uint2*)&Ps[r0 * PSTR + colp]       = p0;
            *(uint2*)&Ps[(r0 + 8) * PSTR + colp] = p1;
        }
        __syncthreads();                   // publish P + al

#pragma unroll
        for (int mt = 0; mt < 4; mt++) {
            float a0 = al_s[wm2 + mt * 16 + lr];
            float a1 = al_s[wm2 + mt * 16 + lr + 8];
#pragma unroll
            for (int nt = 0; nt < 4; nt++) {
                o[mt][nt][0] *= a0; o[mt][nt][1] *= a0;
                o[mt][nt][2] *= a1; o[mt][nt][3] *= a1;
            }
        }

        const uint32_t v_lane = vst_u + (uint32_t)(((wn2 + lb_r) * VSTR + lb_c) * 4);
        uint32_t pa[2][4][4], pb[2][2][4];
#pragma unroll
        for (int mt = 0; mt < 4; mt++)
            ldsm4(pa[0][mt], p_lane + (uint32_t)((mt * 16 * PSTR) * 4));
#pragma unroll
        for (int p = 0; p < 2; p++)
            ldsm4(pb[0][p], v_lane + (uint32_t)((p * 16 * VSTR) * 4));

#pragma unroll
        for (int ksx = 0; ksx < 8; ksx++) {
            const int cur = ksx & 1;
            if (ksx < 7) {
                const int kbn = (ksx + 1) * 8;
#pragma unroll
                for (int mt = 0; mt < 4; mt++)
                    ldsm4(pa[cur ^ 1][mt], p_lane + (uint32_t)((mt * 16 * PSTR + kbn) * 4));
#pragma unroll
                for (int p = 0; p < 2; p++)
                    ldsm4(pb[cur ^ 1][p], v_lane + (uint32_t)((p * 16 * VSTR + kbn) * 4));
            }
#pragma unroll
            for (int mt = 0; mt < 4; mt++) {
                mma_tf32(o[mt][0], pa[cur][mt], pb[cur][0]);
                mma_tf32(o[mt][1], pa[cur][mt], pb[cur][0] + 2);
                mma_tf32(o[mt][2], pa[cur][mt], pb[cur][1]);
                mma_tf32(o[mt][3], pa[cur][mt], pb[cur][1] + 2);
            }
        }
        // no end barrier: next iteration's top barrier protects stage reuse
    }
#undef ISSUE_K_F
#undef ISSUE_V_F

    if (lc == 0) {
        l_s[r0] = l0;
        l_s[r0 + 8] = l1;
    }
    __syncthreads();

    const int b = bh >> 4, h = bh & 15;
#pragma unroll
    for (int mt = 0; mt < 4; mt++) {
        int rloc = wm2 + mt * 16 + lr;
        int row0 = qt * FBQ + rloc;
        float il0 = 1.f / l_s[rloc];
        float il1 = 1.f / l_s[rloc + 8];
        float* out0 = ctx + (size_t)(b * S_ + row0) * H_ + h * HD_ + wn2;
        float* out1 = out0 + (size_t)8 * H_;
#pragma unroll
        for (int nt = 0; nt < 4; nt++) {
            int col = nt * 8 + 2 * lc;
            float2 v0 = { f2tff(o[mt][nt][0] * il0), f2tff(o[mt][nt][1] * il0) };
            float2 v1 = { f2tff(o[mt][nt][2] * il1), f2tff(o[mt][nt][3] * il1) };
            *(float2*)(out0 + col) = v0;
            *(float2*)(out1 + col) = v1;
        }
    }
}

// ---------------- launch ----------------
extern "C" void kernel_launch(void* const* d_in, const int* in_sizes, int n_in,
                              void* d_out, int out_size)
{
    const float* hidden = (const float*)d_in[0];
    const float* cosb   = (const float*)d_in[1];
    const float* sinb   = (const float*)d_in[2];
    // d_in[3]: attention_mask (pure causal -> implemented directly)
    const float* logn   = (const float*)d_in[4];
    const float* Wc     = (const float*)d_in[5];
    const float* bc     = (const float*)d_in[6];
    const float* Wp     = (const float*)d_in[7];
    const float* bp     = (const float*)d_in[8];
    float* out = (float*)d_out;

    float *Q, *Kt, *Vt, *ctx, *hid_tf, *wct, *wpt;
    cudaGetSymbolAddress((void**)&Q,      g_q);
    cudaGetSymbolAddress((void**)&Kt,     g_k);
    cudaGetSymbolAddress((void**)&Vt,     g_v);
    cudaGetSymbolAddress((void**)&ctx,    g_ctx);
    cudaGetSymbolAddress((void**)&hid_tf, g_hid_tf);
    cudaGetSymbolAddress((void**)&wct,    g_wct);
    cudaGetSymbolAddress((void**)&wpt,    g_wpt);

    cudaFuncSetAttribute(gemm_tf32,
                         cudaFuncAttributeMaxDynamicSharedMemorySize, GEMM_SMEM);
    cudaFuncSetAttribute(gemm_qkv,
                         cudaFuncAttributeMaxDynamicSharedMemorySize, GEMM_SMEM);
    cudaFuncSetAttribute(flash_tc,
                         cudaFuncAttributeMaxDynamicSharedMemorySize, FLASH_SMEM);

    // 0) pre-round A + transpose/round weights (one launch)
    prep_all<<<PREP_H + PREP_WC + PREP_WP, 256>>>(hidden, Wc, Wp, hid_tf, wct, wpt);

    // 1) fused QKV GEMM + rope/logn/V-transpose -> g_q, g_k, g_v
    gemm_qkv<<<dim3(QKV_N / 128, ROWS_ / 128), 256, GEMM_SMEM>>>(
        hid_tf, wct, bc, cosb, sinb, logn, Q, Kt, Vt, ROWS_, QKV_N, H_);

    // 2) flash attention -> ctx [4096, 2048]
    flash_tc<<<dim3(S_ / FBQ, B_ * NH_), 256, FLASH_SMEM>>>(Q, Kt, Vt, ctx);

    // 3) out = ctx @ Wp + bp      [4096,2048]
    gemm_tf32<<<dim3(H_ / 128, ROWS_ / 128), 256, GEMM_SMEM>>>(
        ctx, wpt, bp, out, ROWS_, H_, H_);
}